// round 4
// baseline (speedup 1.0000x reference)
#include <cuda_runtime.h>
#include <math.h>

// Problem constants
#define BB 8
#define NN 2048
#define CC 1024
#define KKEEP 1638

// Scratch (allocation-free rule: __device__ globals)
__device__ float g_Q[BB * NN * CC];
__device__ float g_K[BB * NN * CC];
__device__ float g_V[BB * NN * CC];
__device__ float g_S[(size_t)BB * NN * NN];

#define PLANE 2176  // 16 * 136 words per smem plane

// ---------------------------------------------------------------------------
// TF32 helpers
// ---------------------------------------------------------------------------
__device__ __forceinline__ unsigned f2tf32(float x) {
    unsigned r;
    asm("cvt.rna.tf32.f32 %0, %1;" : "=r"(r) : "f"(x));
    return r;
}

__device__ __forceinline__ void mma8(float* c, const unsigned* a, const unsigned* b) {
    asm volatile(
        "mma.sync.aligned.m16n8k8.row.col.f32.tf32.tf32.f32 "
        "{%0,%1,%2,%3}, {%4,%5,%6,%7}, {%8,%9}, {%0,%1,%2,%3};"
        : "+f"(c[0]), "+f"(c[1]), "+f"(c[2]), "+f"(c[3])
        : "r"(a[0]), "r"(a[1]), "r"(a[2]), "r"(a[3]), "r"(b[0]), "r"(b[1]));
}

// ---------------------------------------------------------------------------
// Tensor-core GEMM, 128x128x16 tile, 256 threads, 8 warps (2x4) of 64x32.
// TF32 hi/lo split is PRE-COMPUTED into smem planes by the loader threads, so
// the mainloop is pure LDS + HMMA.
//   THREEX: 1 -> 3xTF32 (fp32-accurate: al*bh + ah*bl + ah*bh), 0 -> 1xTF32
//   TRANSB: true  -> B is [N,K] row-major (NT), false -> B is [K,N] (NN)
//   BIAS:   add bias[n]
// C[m][n] = scale * sum_k A[m][k]*Bop[k][n] (+ bias[n]); batched over z.
// smem layout per buffer: AH [AL] BH [BL], each PLANE words, double-buffered.
// ---------------------------------------------------------------------------
template <int THREEX, bool TRANSB, bool BIAS>
__global__ void __launch_bounds__(256, 1)
mma_gemm(const float* __restrict__ A, const float* __restrict__ B,
         float* __restrict__ C, const float* __restrict__ bias,
         int M, int N, int K,
         long long sA, long long sB, long long sC, float scale) {
    extern __shared__ unsigned sm[];
    const int NPA = THREEX ? 2 : 1;           // planes per matrix
    const int BUFW = 2 * NPA * PLANE;         // words per buffer

    A += (size_t)blockIdx.z * sA;
    B += (size_t)blockIdx.z * sB;
    C += (size_t)blockIdx.z * sC;

    const int t = threadIdx.x;
    const int lane = t & 31;
    const int warp = t >> 5;
    const int wm = warp & 1;   // 2 warps along M
    const int wn = warp >> 1;  // 4 warps along N
    const int g = lane >> 2;   // 0..7
    const int tg = lane & 3;   // 0..3

    const int m0 = blockIdx.y * 128;
    const int n0 = blockIdx.x * 128;
    const int aBase = wm * 64;
    const int bBase = wn * 32;

    float acc[4][4][4];
#pragma unroll
    for (int i = 0; i < 4; i++)
#pragma unroll
        for (int j = 0; j < 4; j++)
#pragma unroll
            for (int r = 0; r < 4; r++) acc[i][j][r] = 0.f;

    const int NK = K / 16;
    float4 ra[2], rb[2];

    // --- global load of tile kt into registers ---
    auto load_tile = [&](int kt) {
        const int k0 = kt * 16;
#pragma unroll
        for (int i = 0; i < 2; i++) {
            int idx = t + i * 256;
            int row = idx >> 2, kq = idx & 3;
            ra[i] = *(const float4*)&A[(size_t)(m0 + row) * K + k0 + kq * 4];
        }
        if (TRANSB) {
#pragma unroll
            for (int i = 0; i < 2; i++) {
                int idx = t + i * 256;
                int row = idx >> 2, kq = idx & 3;
                rb[i] = *(const float4*)&B[(size_t)(n0 + row) * K + k0 + kq * 4];
            }
        } else {
#pragma unroll
            for (int i = 0; i < 2; i++) {
                int idx = t + i * 256;
                int kk = idx >> 5, n4 = (idx & 31) * 4;
                rb[i] = *(const float4*)&B[(size_t)(k0 + kk) * N + n0 + n4];
            }
        }
    };

    // --- split + store registers into smem planes of buffer buf ---
    auto store_tile = [&](int buf) {
        unsigned* AH = sm + buf * BUFW;
        unsigned* AL = AH + PLANE;            // valid only if THREEX
        unsigned* BH = AH + NPA * PLANE;
        unsigned* BL = BH + PLANE;
#pragma unroll
        for (int i = 0; i < 2; i++) {
            int idx = t + i * 256;
            int row = idx >> 2, kq = idx & 3;
            float v[4] = {ra[i].x, ra[i].y, ra[i].z, ra[i].w};
#pragma unroll
            for (int j = 0; j < 4; j++) {
                unsigned hi = f2tf32(v[j]);
                AH[(kq * 4 + j) * 136 + row] = hi;
                if (THREEX)
                    AL[(kq * 4 + j) * 136 + row] = f2tf32(v[j] - __uint_as_float(hi));
            }
        }
        if (TRANSB) {
#pragma unroll
            for (int i = 0; i < 2; i++) {
                int idx = t + i * 256;
                int row = idx >> 2, kq = idx & 3;
                float v[4] = {rb[i].x, rb[i].y, rb[i].z, rb[i].w};
#pragma unroll
                for (int j = 0; j < 4; j++) {
                    unsigned hi = f2tf32(v[j]);
                    BH[(kq * 4 + j) * 136 + row] = hi;
                    if (THREEX)
                        BL[(kq * 4 + j) * 136 + row] = f2tf32(v[j] - __uint_as_float(hi));
                }
            }
        } else {
#pragma unroll
            for (int i = 0; i < 2; i++) {
                int idx = t + i * 256;
                int kk = idx >> 5, n4 = (idx & 31) * 4;
                float v[4] = {rb[i].x, rb[i].y, rb[i].z, rb[i].w};
#pragma unroll
                for (int j = 0; j < 4; j++) {
                    unsigned hi = f2tf32(v[j]);
                    BH[kk * 136 + n4 + j] = hi;
                    if (THREEX)
                        BL[kk * 136 + n4 + j] = f2tf32(v[j] - __uint_as_float(hi));
                }
            }
        }
    };

    load_tile(0);
    store_tile(0);
    __syncthreads();

    for (int kt = 0; kt < NK; kt++) {
        const int buf = kt & 1;
        if (kt + 1 < NK) load_tile(kt + 1);

        const unsigned* AH = sm + buf * BUFW;
        const unsigned* AL = AH + PLANE;
        const unsigned* BH = AH + NPA * PLANE;
        const unsigned* BL = BH + PLANE;

#pragma unroll
        for (int ks = 0; ks < 16; ks += 8) {
            unsigned ah[4][4], bh[4][2];
#pragma unroll
            for (int mt = 0; mt < 4; mt++) {
                int mo = aBase + mt * 16 + g;
                ah[mt][0] = AH[(ks + tg) * 136 + mo];
                ah[mt][1] = AH[(ks + tg) * 136 + mo + 8];
                ah[mt][2] = AH[(ks + tg + 4) * 136 + mo];
                ah[mt][3] = AH[(ks + tg + 4) * 136 + mo + 8];
            }
#pragma unroll
            for (int nt = 0; nt < 4; nt++) {
                int no = bBase + nt * 8 + g;
                bh[nt][0] = BH[(ks + tg) * 136 + no];
                bh[nt][1] = BH[(ks + tg + 4) * 136 + no];
            }

            if (THREEX) {
                unsigned al[4][4], bl[4][2];
#pragma unroll
                for (int mt = 0; mt < 4; mt++) {
                    int mo = aBase + mt * 16 + g;
                    al[mt][0] = AL[(ks + tg) * 136 + mo];
                    al[mt][1] = AL[(ks + tg) * 136 + mo + 8];
                    al[mt][2] = AL[(ks + tg + 4) * 136 + mo];
                    al[mt][3] = AL[(ks + tg + 4) * 136 + mo + 8];
                }
#pragma unroll
                for (int nt = 0; nt < 4; nt++) {
                    int no = bBase + nt * 8 + g;
                    bl[nt][0] = BL[(ks + tg) * 136 + no];
                    bl[nt][1] = BL[(ks + tg + 4) * 136 + no];
                }
#pragma unroll
                for (int mt = 0; mt < 4; mt++)
#pragma unroll
                    for (int nt = 0; nt < 4; nt++) {
                        mma8(acc[mt][nt], al[mt], bh[nt]);
                        mma8(acc[mt][nt], ah[mt], bl[nt]);
                        mma8(acc[mt][nt], ah[mt], bh[nt]);
                    }
            } else {
#pragma unroll
                for (int mt = 0; mt < 4; mt++)
#pragma unroll
                    for (int nt = 0; nt < 4; nt++) mma8(acc[mt][nt], ah[mt], bh[nt]);
            }
        }

        // Store next tile into the other buffer (not read by current compute);
        // the single barrier below orders it against next iteration's reads.
        if (kt + 1 < NK) store_tile((kt + 1) & 1);
        __syncthreads();
    }

    // --- epilogue ---
#pragma unroll
    for (int mt = 0; mt < 4; mt++) {
        int m = m0 + aBase + mt * 16 + g;
#pragma unroll
        for (int nt = 0; nt < 4; nt++) {
            int n = n0 + bBase + nt * 8 + tg * 2;
            float b0 = 0.f, b1 = 0.f;
            if (BIAS) { b0 = bias[n]; b1 = bias[n + 1]; }
            float2 v0 = make_float2(acc[mt][nt][0] * scale + b0,
                                    acc[mt][nt][1] * scale + b1);
            float2 v1 = make_float2(acc[mt][nt][2] * scale + b0,
                                    acc[mt][nt][3] * scale + b1);
            *(float2*)&C[(size_t)m * N + n] = v0;
            *(float2*)&C[(size_t)(m + 8) * N + n] = v1;
        }
    }
}

// ---------------------------------------------------------------------------
// Per-row exact top-k threshold (4-pass MSB radix select) + masked softmax.
// One block (256 threads) per row of 2048. Masked entries -> exactly 0.
// ---------------------------------------------------------------------------
__device__ __forceinline__ unsigned f2u(float f) {
    unsigned b = __float_as_uint(f);
    return (b & 0x80000000u) ? ~b : (b | 0x80000000u);
}
__device__ __forceinline__ float u2f(unsigned u) {
    unsigned b = (u & 0x80000000u) ? (u & 0x7fffffffu) : ~u;
    return __uint_as_float(b);
}

__global__ void __launch_bounds__(256) topk_softmax(float* __restrict__ S) {
    const size_t row = blockIdx.x;
    float* p = S + row * NN;
    const int tid = threadIdx.x;  // 256 threads, 8 elems each

    __shared__ int hist[256];
    __shared__ int s_digit, s_rem;
    __shared__ unsigned s_warpk[8];
    __shared__ float s_warpf[8];
    __shared__ float s_sum;

    unsigned key[8];
    float val[8];
    unsigned lmax = 0;
#pragma unroll
    for (int i = 0; i < 8; i++) {
        float f = p[tid + i * 256];
        val[i] = f;
        key[i] = f2u(f);
        lmax = max(lmax, key[i]);
    }

    lmax = __reduce_max_sync(0xffffffffu, lmax);
    if ((tid & 31) == 0) s_warpk[tid >> 5] = lmax;
    __syncthreads();
    if (tid == 0) {
        unsigned m = s_warpk[0];
#pragma unroll
        for (int w = 1; w < 8; w++) m = max(m, s_warpk[w]);
        s_warpk[0] = m;
        s_rem = KKEEP;
    }

    unsigned prefix = 0, pmask = 0;
    for (int shift = 24; shift >= 0; shift -= 8) {
        hist[tid] = 0;
        __syncthreads();
#pragma unroll
        for (int i = 0; i < 8; i++)
            if ((key[i] & pmask) == prefix)
                atomicAdd(&hist[(key[i] >> shift) & 255], 1);
        __syncthreads();
        if (tid == 0) {
            int remk = s_rem, cum = 0, d = 255;
            for (; d > 0; --d) {
                int c = hist[d];
                if (cum + c >= remk) break;
                cum += c;
            }
            s_digit = d;
            s_rem = remk - cum;
        }
        __syncthreads();
        prefix |= ((unsigned)s_digit) << shift;
        pmask |= 0xFFu << shift;
    }
    const unsigned thr = prefix;
    const float mval = u2f(s_warpk[0]);

    float e[8];
    float lsum = 0.f;
#pragma unroll
    for (int i = 0; i < 8; i++) {
        if (key[i] >= thr) {
            e[i] = __expf(val[i] - mval);
            lsum += e[i];
        } else {
            e[i] = 0.f;
        }
    }
#pragma unroll
    for (int o = 16; o > 0; o >>= 1) lsum += __shfl_down_sync(0xffffffffu, lsum, o);
    if ((tid & 31) == 0) s_warpf[tid >> 5] = lsum;
    __syncthreads();
    if (tid == 0) {
        float s = 0.f;
#pragma unroll
        for (int w = 0; w < 8; w++) s += s_warpf[w];
        s_sum = s;
    }
    __syncthreads();
    const float inv = 1.0f / s_sum;
#pragma unroll
    for (int i = 0; i < 8; i++) p[tid + i * 256] = e[i] * inv;
}

// ---------------------------------------------------------------------------
// Launch
// ---------------------------------------------------------------------------
extern "C" void kernel_launch(void* const* d_in, const int* in_sizes, int n_in,
                              void* d_out, int out_size) {
    const float* x  = (const float*)d_in[0];
    const float* Wq = (const float*)d_in[1];
    const float* bq = (const float*)d_in[2];
    const float* Wk = (const float*)d_in[3];
    const float* bk = (const float*)d_in[4];
    const float* Wv = (const float*)d_in[5];
    const float* bv = (const float*)d_in[6];
    float* out = (float*)d_out;

    float *Q, *K, *V, *S;
    cudaGetSymbolAddress((void**)&Q, g_Q);
    cudaGetSymbolAddress((void**)&K, g_K);
    cudaGetSymbolAddress((void**)&V, g_V);
    cudaGetSymbolAddress((void**)&S, g_S);

    const size_t smem3 = (size_t)2 * 4 * PLANE * 4;  // 69632 B (hi+lo planes)
    const size_t smem1 = (size_t)2 * 2 * PLANE * 4;  // 34816 B (hi only)

    cudaFuncSetAttribute(mma_gemm<1, true, true>,
                         cudaFuncAttributeMaxDynamicSharedMemorySize, (int)smem3);
    cudaFuncSetAttribute(mma_gemm<1, true, false>,
                         cudaFuncAttributeMaxDynamicSharedMemorySize, (int)smem3);
    cudaFuncSetAttribute(mma_gemm<0, true, true>,
                         cudaFuncAttributeMaxDynamicSharedMemorySize, (int)smem1);
    cudaFuncSetAttribute(mma_gemm<0, false, false>,
                         cudaFuncAttributeMaxDynamicSharedMemorySize, (int)smem1);

    dim3 thr(256);

    // QKV projections: [16384,1024] x [1024,1024]^T + bias
    dim3 gqkv(CC / 128, (BB * NN) / 128, 1);
    // Q, K feed the top-k logits -> need fp32-grade accuracy (3xTF32)
    mma_gemm<1, true, true><<<gqkv, thr, smem3>>>(x, Wq, Q, bq, BB * NN, CC, CC, 0, 0, 0, 1.0f);
    mma_gemm<1, true, true><<<gqkv, thr, smem3>>>(x, Wk, K, bk, BB * NN, CC, CC, 0, 0, 0, 1.0f);
    // V only perturbs the output linearly -> 1xTF32 is fine
    mma_gemm<0, true, true><<<gqkv, thr, smem1>>>(x, Wv, V, bv, BB * NN, CC, CC, 0, 0, 0, 1.0f);

    // S = Q K^T / sqrt(C): accuracy-critical (top-k boundary) -> 3xTF32
    dim3 gs(NN / 128, NN / 128, BB);
    mma_gemm<1, true, false><<<gs, thr, smem3>>>(Q, K, S, nullptr, NN, NN, CC,
                                                 (long long)NN * CC, (long long)NN * CC,
                                                 (long long)NN * NN, 0.03125f);

    // exact top-k mask + softmax (in place)
    topk_softmax<<<BB * NN, 256>>>(S);

    // O = P V (1xTF32)
    dim3 go(CC / 128, NN / 128, BB);
    mma_gemm<0, false, false><<<go, thr, smem1>>>(S, V, out, nullptr, NN, CC, NN,
                                                  (long long)NN * NN, (long long)NN * CC,
                                                  (long long)NN * CC, 1.0f);
}

// round 5
// speedup vs baseline: 1.7243x; 1.7243x over previous
#include <cuda_runtime.h>
#include <cuda_bf16.h>
#include <math.h>

// Problem constants
#define BB 8
#define NN 2048
#define CC 1024
#define KKEEP 1638

// Scratch (allocation-free rule: __device__ globals)
__device__ float g_Q[BB * NN * CC];
__device__ float g_K[BB * NN * CC];
__device__ float g_V[BB * NN * CC];
__device__ float g_S[(size_t)BB * NN * NN];

// smem plane: 8 k-pair rows x (128 + 8 pad) packed-bf16x2 words
#define PADW 136
#define PLANE (8 * PADW)      // 1088 words
#define BUFW (4 * PLANE)      // AH, AL, BH, BL per buffer

// ---------------------------------------------------------------------------
// bf16 split helpers: v = hi + lo + O(2^-18 |v|)
// Packs two k-adjacent values into one .b32 (low 16 = even k).
// ---------------------------------------------------------------------------
__device__ __forceinline__ void split2(float v0, float v1, unsigned& hi, unsigned& lo) {
    __nv_bfloat162 h = __floats2bfloat162_rn(v0, v1);
    float2 hf = __bfloat1622float2(h);
    __nv_bfloat162 l = __floats2bfloat162_rn(v0 - hf.x, v1 - hf.y);
    hi = *reinterpret_cast<unsigned*>(&h);
    lo = *reinterpret_cast<unsigned*>(&l);
}

__device__ __forceinline__ void mma16(float* c, const unsigned* a, const unsigned* b) {
    asm volatile(
        "mma.sync.aligned.m16n8k16.row.col.f32.bf16.bf16.f32 "
        "{%0,%1,%2,%3}, {%4,%5,%6,%7}, {%8,%9}, {%0,%1,%2,%3};"
        : "+f"(c[0]), "+f"(c[1]), "+f"(c[2]), "+f"(c[3])
        : "r"(a[0]), "r"(a[1]), "r"(a[2]), "r"(a[3]), "r"(b[0]), "r"(b[1]));
}

// ---------------------------------------------------------------------------
// fp32-accurate GEMM via 3-term bf16 split on tensor cores.
// 128x128x16 tile, 256 threads, 8 warps (2x4) each owning 64x32.
//   TRANSB: true  -> B is [N,K] row-major (NT), false -> B is [K,N] (NN)
//   BIAS:   add bias[n]
// C[m][n] = scale * sum_k A[m][k]*Bop[k][n] (+ bias[n]); batched over z.
// ---------------------------------------------------------------------------
template <bool TRANSB, bool BIAS>
__global__ void __launch_bounds__(256, 2)
mma_gemm(const float* __restrict__ A, const float* __restrict__ B,
         float* __restrict__ C, const float* __restrict__ bias,
         int M, int N, int K,
         long long sA, long long sB, long long sC, float scale) {
    __shared__ unsigned sm[2 * BUFW];

    A += (size_t)blockIdx.z * sA;
    B += (size_t)blockIdx.z * sB;
    C += (size_t)blockIdx.z * sC;

    const int t = threadIdx.x;
    const int lane = t & 31;
    const int warp = t >> 5;
    const int wm = warp & 1;   // 2 warps along M
    const int wn = warp >> 1;  // 4 warps along N
    const int g = lane >> 2;   // 0..7
    const int tg = lane & 3;   // 0..3

    const int m0 = blockIdx.y * 128;
    const int n0 = blockIdx.x * 128;
    const int aBase = wm * 64;
    const int bBase = wn * 32;

    float acc[4][4][4];
#pragma unroll
    for (int i = 0; i < 4; i++)
#pragma unroll
        for (int j = 0; j < 4; j++)
#pragma unroll
            for (int r = 0; r < 4; r++) acc[i][j][r] = 0.f;

    const int NK = K / 16;
    float4 ra[2], rb[2];

    // --- global load of tile kt into registers ---
    auto load_tile = [&](int kt) {
        const int k0 = kt * 16;
#pragma unroll
        for (int i = 0; i < 2; i++) {
            int idx = t + i * 256;
            int row = idx >> 2, kq = idx & 3;
            ra[i] = *(const float4*)&A[(size_t)(m0 + row) * K + k0 + kq * 4];
        }
        if (TRANSB) {
#pragma unroll
            for (int i = 0; i < 2; i++) {
                int idx = t + i * 256;
                int row = idx >> 2, kq = idx & 3;
                rb[i] = *(const float4*)&B[(size_t)(n0 + row) * K + k0 + kq * 4];
            }
        } else {
            // B [K,N]: thread owns k-pair kp = t>>5, cols n4..n4+3
            int kp = t >> 5, n4 = (t & 31) * 4;
            rb[0] = *(const float4*)&B[(size_t)(k0 + 2 * kp) * N + n0 + n4];
            rb[1] = *(const float4*)&B[(size_t)(k0 + 2 * kp + 1) * N + n0 + n4];
        }
    };

    // --- split to bf16 hi/lo planes in smem buffer buf ---
    auto store_tile = [&](int buf) {
        unsigned* AH = sm + buf * BUFW;
        unsigned* AL = AH + PLANE;
        unsigned* BH = AH + 2 * PLANE;
        unsigned* BL = AH + 3 * PLANE;
#pragma unroll
        for (int i = 0; i < 2; i++) {
            int idx = t + i * 256;
            int row = idx >> 2, kq = idx & 3;
            unsigned h, l;
            split2(ra[i].x, ra[i].y, h, l);
            AH[(kq * 2) * PADW + row] = h;
            AL[(kq * 2) * PADW + row] = l;
            split2(ra[i].z, ra[i].w, h, l);
            AH[(kq * 2 + 1) * PADW + row] = h;
            AL[(kq * 2 + 1) * PADW + row] = l;
        }
        if (TRANSB) {
#pragma unroll
            for (int i = 0; i < 2; i++) {
                int idx = t + i * 256;
                int row = idx >> 2, kq = idx & 3;
                unsigned h, l;
                split2(rb[i].x, rb[i].y, h, l);
                BH[(kq * 2) * PADW + row] = h;
                BL[(kq * 2) * PADW + row] = l;
                split2(rb[i].z, rb[i].w, h, l);
                BH[(kq * 2 + 1) * PADW + row] = h;
                BL[(kq * 2 + 1) * PADW + row] = l;
            }
        } else {
            int kp = t >> 5, n4 = (t & 31) * 4;
            const float f0[4] = {rb[0].x, rb[0].y, rb[0].z, rb[0].w};
            const float f1[4] = {rb[1].x, rb[1].y, rb[1].z, rb[1].w};
            unsigned h[4], l[4];
#pragma unroll
            for (int j = 0; j < 4; j++) split2(f0[j], f1[j], h[j], l[j]);
            *(uint4*)&BH[kp * PADW + n4] = make_uint4(h[0], h[1], h[2], h[3]);
            *(uint4*)&BL[kp * PADW + n4] = make_uint4(l[0], l[1], l[2], l[3]);
        }
    };

    load_tile(0);
    store_tile(0);
    __syncthreads();

    for (int kt = 0; kt < NK; kt++) {
        const int buf = kt & 1;
        if (kt + 1 < NK) load_tile(kt + 1);

        const unsigned* AH = sm + buf * BUFW;
        const unsigned* AL = AH + PLANE;
        const unsigned* BH = AH + 2 * PLANE;
        const unsigned* BL = AH + 3 * PLANE;

        // Phase 1: ah * bh
        unsigned ah[4][4], bh[4][2];
#pragma unroll
        for (int mt = 0; mt < 4; mt++) {
            int mo = aBase + mt * 16 + g;
            ah[mt][0] = AH[tg * PADW + mo];
            ah[mt][1] = AH[tg * PADW + mo + 8];
            ah[mt][2] = AH[(tg + 4) * PADW + mo];
            ah[mt][3] = AH[(tg + 4) * PADW + mo + 8];
        }
#pragma unroll
        for (int nt = 0; nt < 4; nt++) {
            int no = bBase + nt * 8 + g;
            bh[nt][0] = BH[tg * PADW + no];
            bh[nt][1] = BH[(tg + 4) * PADW + no];
        }
#pragma unroll
        for (int mt = 0; mt < 4; mt++)
#pragma unroll
            for (int nt = 0; nt < 4; nt++) mma16(acc[mt][nt], ah[mt], bh[nt]);

        // Phase 2: ah * bl
        {
            unsigned bl[4][2];
#pragma unroll
            for (int nt = 0; nt < 4; nt++) {
                int no = bBase + nt * 8 + g;
                bl[nt][0] = BL[tg * PADW + no];
                bl[nt][1] = BL[(tg + 4) * PADW + no];
            }
#pragma unroll
            for (int mt = 0; mt < 4; mt++)
#pragma unroll
                for (int nt = 0; nt < 4; nt++) mma16(acc[mt][nt], ah[mt], bl[nt]);
        }

        // Phase 3: al * bh
        {
            unsigned al[4][4];
#pragma unroll
            for (int mt = 0; mt < 4; mt++) {
                int mo = aBase + mt * 16 + g;
                al[mt][0] = AL[tg * PADW + mo];
                al[mt][1] = AL[tg * PADW + mo + 8];
                al[mt][2] = AL[(tg + 4) * PADW + mo];
                al[mt][3] = AL[(tg + 4) * PADW + mo + 8];
            }
#pragma unroll
            for (int mt = 0; mt < 4; mt++)
#pragma unroll
                for (int nt = 0; nt < 4; nt++) mma16(acc[mt][nt], al[mt], bh[nt]);
        }

        __syncthreads();
        if (kt + 1 < NK) {
            store_tile((kt + 1) & 1);
            __syncthreads();
        }
    }

    // --- epilogue ---
#pragma unroll
    for (int mt = 0; mt < 4; mt++) {
        int m = m0 + aBase + mt * 16 + g;
#pragma unroll
        for (int nt = 0; nt < 4; nt++) {
            int n = n0 + bBase + nt * 8 + tg * 2;
            float b0 = 0.f, b1 = 0.f;
            if (BIAS) { b0 = bias[n]; b1 = bias[n + 1]; }
            float2 v0 = make_float2(acc[mt][nt][0] * scale + b0,
                                    acc[mt][nt][1] * scale + b1);
            float2 v1 = make_float2(acc[mt][nt][2] * scale + b0,
                                    acc[mt][nt][3] * scale + b1);
            *(float2*)&C[(size_t)m * N + n] = v0;
            *(float2*)&C[(size_t)(m + 8) * N + n] = v1;
        }
    }
}

// ---------------------------------------------------------------------------
// Per-row exact top-k threshold (4-pass MSB radix select) + masked softmax.
// One block (256 threads) per row of 2048. Masked entries -> exactly 0.
// ---------------------------------------------------------------------------
__device__ __forceinline__ unsigned f2u(float f) {
    unsigned b = __float_as_uint(f);
    return (b & 0x80000000u) ? ~b : (b | 0x80000000u);
}
__device__ __forceinline__ float u2f(unsigned u) {
    unsigned b = (u & 0x80000000u) ? (u & 0x7fffffffu) : ~u;
    return __uint_as_float(b);
}

__global__ void __launch_bounds__(256) topk_softmax(float* __restrict__ S) {
    const size_t row = blockIdx.x;
    float* p = S + row * NN;
    const int tid = threadIdx.x;  // 256 threads, 8 elems each

    __shared__ int hist[256];
    __shared__ int s_digit, s_rem;
    __shared__ unsigned s_warpk[8];
    __shared__ float s_warpf[8];
    __shared__ float s_sum;

    unsigned key[8];
    float val[8];
    unsigned lmax = 0;
#pragma unroll
    for (int i = 0; i < 8; i++) {
        float f = p[tid + i * 256];
        val[i] = f;
        key[i] = f2u(f);
        lmax = max(lmax, key[i]);
    }

    lmax = __reduce_max_sync(0xffffffffu, lmax);
    if ((tid & 31) == 0) s_warpk[tid >> 5] = lmax;
    __syncthreads();
    if (tid == 0) {
        unsigned m = s_warpk[0];
#pragma unroll
        for (int w = 1; w < 8; w++) m = max(m, s_warpk[w]);
        s_warpk[0] = m;
        s_rem = KKEEP;
    }

    unsigned prefix = 0, pmask = 0;
    for (int shift = 24; shift >= 0; shift -= 8) {
        hist[tid] = 0;
        __syncthreads();
#pragma unroll
        for (int i = 0; i < 8; i++)
            if ((key[i] & pmask) == prefix)
                atomicAdd(&hist[(key[i] >> shift) & 255], 1);
        __syncthreads();
        if (tid == 0) {
            int remk = s_rem, cum = 0, d = 255;
            for (; d > 0; --d) {
                int c = hist[d];
                if (cum + c >= remk) break;
                cum += c;
            }
            s_digit = d;
            s_rem = remk - cum;
        }
        __syncthreads();
        prefix |= ((unsigned)s_digit) << shift;
        pmask |= 0xFFu << shift;
    }
    const unsigned thr = prefix;
    const float mval = u2f(s_warpk[0]);

    float e[8];
    float lsum = 0.f;
#pragma unroll
    for (int i = 0; i < 8; i++) {
        if (key[i] >= thr) {
            e[i] = __expf(val[i] - mval);
            lsum += e[i];
        } else {
            e[i] = 0.f;
        }
    }
#pragma unroll
    for (int o = 16; o > 0; o >>= 1) lsum += __shfl_down_sync(0xffffffffu, lsum, o);
    if ((tid & 31) == 0) s_warpf[tid >> 5] = lsum;
    __syncthreads();
    if (tid == 0) {
        float s = 0.f;
#pragma unroll
        for (int w = 0; w < 8; w++) s += s_warpf[w];
        s_sum = s;
    }
    __syncthreads();
    const float inv = 1.0f / s_sum;
#pragma unroll
    for (int i = 0; i < 8; i++) p[tid + i * 256] = e[i] * inv;
}

// ---------------------------------------------------------------------------
// Launch
// ---------------------------------------------------------------------------
extern "C" void kernel_launch(void* const* d_in, const int* in_sizes, int n_in,
                              void* d_out, int out_size) {
    const float* x  = (const float*)d_in[0];
    const float* Wq = (const float*)d_in[1];
    const float* bq = (const float*)d_in[2];
    const float* Wk = (const float*)d_in[3];
    const float* bk = (const float*)d_in[4];
    const float* Wv = (const float*)d_in[5];
    const float* bv = (const float*)d_in[6];
    float* out = (float*)d_out;

    float *Q, *K, *V, *S;
    cudaGetSymbolAddress((void**)&Q, g_Q);
    cudaGetSymbolAddress((void**)&K, g_K);
    cudaGetSymbolAddress((void**)&V, g_V);
    cudaGetSymbolAddress((void**)&S, g_S);

    dim3 thr(256);

    // QKV projections: [16384,1024] x [1024,1024]^T + bias
    dim3 gqkv(CC / 128, (BB * NN) / 128, 1);
    mma_gemm<true, true><<<gqkv, thr>>>(x, Wq, Q, bq, BB * NN, CC, CC, 0, 0, 0, 1.0f);
    mma_gemm<true, true><<<gqkv, thr>>>(x, Wk, K, bk, BB * NN, CC, CC, 0, 0, 0, 1.0f);
    mma_gemm<true, true><<<gqkv, thr>>>(x, Wv, V, bv, BB * NN, CC, CC, 0, 0, 0, 1.0f);

    // S = Q K^T / sqrt(C), batched over B
    dim3 gs(NN / 128, NN / 128, BB);
    mma_gemm<true, false><<<gs, thr>>>(Q, K, S, nullptr, NN, NN, CC,
                                       (long long)NN * CC, (long long)NN * CC,
                                       (long long)NN * NN, 0.03125f);

    // exact top-k mask + softmax (in place)
    topk_softmax<<<BB * NN, 256>>>(S);

    // O = P V, batched over B
    dim3 go(CC / 128, NN / 128, BB);
    mma_gemm<false, false><<<go, thr>>>(S, V, out, nullptr, NN, CC, NN,
                                        (long long)NN * NN, (long long)NN * CC,
                                        (long long)NN * CC, 1.0f);
}

// round 6
// speedup vs baseline: 1.7250x; 1.0004x over previous
#include <cuda_runtime.h>
#include <cuda_bf16.h>
#include <math.h>

// Problem constants
#define BB 8
#define NN 2048
#define CC 1024
#define KKEEP 1638

// Scratch (allocation-free rule: __device__ globals)
__device__ float g_Q[BB * NN * CC];
__device__ float g_K[BB * NN * CC];
__device__ float g_V[BB * NN * CC];
__device__ float g_S[(size_t)BB * NN * NN];

// smem plane: 8 k-pair rows x (128 + 8 pad) packed-bf16x2 words
#define PADW 136
#define PLANE (8 * PADW)      // 1088 words
#define BUFW (4 * PLANE)      // AH, AL, BH, BL per buffer

// ---------------------------------------------------------------------------
// bf16 split helpers: v = hi + lo + O(2^-18 |v|)
// Packs two k-adjacent values into one .b32 (low 16 = even k).
// ---------------------------------------------------------------------------
__device__ __forceinline__ void split2(float v0, float v1, unsigned& hi, unsigned& lo) {
    __nv_bfloat162 h = __floats2bfloat162_rn(v0, v1);
    float2 hf = __bfloat1622float2(h);
    __nv_bfloat162 l = __floats2bfloat162_rn(v0 - hf.x, v1 - hf.y);
    hi = *reinterpret_cast<unsigned*>(&h);
    lo = *reinterpret_cast<unsigned*>(&l);
}

__device__ __forceinline__ void mma16(float* c, const unsigned* a, const unsigned* b) {
    asm volatile(
        "mma.sync.aligned.m16n8k16.row.col.f32.bf16.bf16.f32 "
        "{%0,%1,%2,%3}, {%4,%5,%6,%7}, {%8,%9}, {%0,%1,%2,%3};"
        : "+f"(c[0]), "+f"(c[1]), "+f"(c[2]), "+f"(c[3])
        : "r"(a[0]), "r"(a[1]), "r"(a[2]), "r"(a[3]), "r"(b[0]), "r"(b[1]));
}

// ---------------------------------------------------------------------------
// fp32-accurate GEMM via 3-term bf16 split on tensor cores.
// 128x128x16 tile, 256 threads, 8 warps (2x4) each owning 64x32.
//   TRANSB: true  -> B is [N,K] row-major (NT), false -> B is [K,N] (NN)
//   BIAS:   add bias[n]
// C[m][n] = scale * sum_k A[m][k]*Bop[k][n] (+ bias[n]); batched over z.
// ---------------------------------------------------------------------------
template <bool TRANSB, bool BIAS>
__global__ void __launch_bounds__(256, 2)
mma_gemm(const float* __restrict__ A, const float* __restrict__ B,
         float* __restrict__ C, const float* __restrict__ bias,
         int M, int N, int K,
         long long sA, long long sB, long long sC, float scale) {
    __shared__ unsigned sm[2 * BUFW];

    A += (size_t)blockIdx.z * sA;
    B += (size_t)blockIdx.z * sB;
    C += (size_t)blockIdx.z * sC;

    const int t = threadIdx.x;
    const int lane = t & 31;
    const int warp = t >> 5;
    const int wm = warp & 1;   // 2 warps along M
    const int wn = warp >> 1;  // 4 warps along N
    const int g = lane >> 2;   // 0..7
    const int tg = lane & 3;   // 0..3

    const int m0 = blockIdx.y * 128;
    const int n0 = blockIdx.x * 128;
    const int aBase = wm * 64;
    const int bBase = wn * 32;

    float acc[4][4][4];
#pragma unroll
    for (int i = 0; i < 4; i++)
#pragma unroll
        for (int j = 0; j < 4; j++)
#pragma unroll
            for (int r = 0; r < 4; r++) acc[i][j][r] = 0.f;

    const int NK = K / 16;
    float4 ra[2], rb[2];

    // --- global load of tile kt into registers ---
    auto load_tile = [&](int kt) {
        const int k0 = kt * 16;
#pragma unroll
        for (int i = 0; i < 2; i++) {
            int idx = t + i * 256;
            int row = idx >> 2, kq = idx & 3;
            ra[i] = *(const float4*)&A[(size_t)(m0 + row) * K + k0 + kq * 4];
        }
        if (TRANSB) {
#pragma unroll
            for (int i = 0; i < 2; i++) {
                int idx = t + i * 256;
                int row = idx >> 2, kq = idx & 3;
                rb[i] = *(const float4*)&B[(size_t)(n0 + row) * K + k0 + kq * 4];
            }
        } else {
            // B [K,N]: thread owns k-pair kp = t>>5, cols n4..n4+3
            int kp = t >> 5, n4 = (t & 31) * 4;
            rb[0] = *(const float4*)&B[(size_t)(k0 + 2 * kp) * N + n0 + n4];
            rb[1] = *(const float4*)&B[(size_t)(k0 + 2 * kp + 1) * N + n0 + n4];
        }
    };

    // --- split to bf16 hi/lo planes in smem buffer buf ---
    auto store_tile = [&](int buf) {
        unsigned* AH = sm + buf * BUFW;
        unsigned* AL = AH + PLANE;
        unsigned* BH = AH + 2 * PLANE;
        unsigned* BL = AH + 3 * PLANE;
#pragma unroll
        for (int i = 0; i < 2; i++) {
            int idx = t + i * 256;
            int row = idx >> 2, kq = idx & 3;
            unsigned h, l;
            split2(ra[i].x, ra[i].y, h, l);
            AH[(kq * 2) * PADW + row] = h;
            AL[(kq * 2) * PADW + row] = l;
            split2(ra[i].z, ra[i].w, h, l);
            AH[(kq * 2 + 1) * PADW + row] = h;
            AL[(kq * 2 + 1) * PADW + row] = l;
        }
        if (TRANSB) {
#pragma unroll
            for (int i = 0; i < 2; i++) {
                int idx = t + i * 256;
                int row = idx >> 2, kq = idx & 3;
                unsigned h, l;
                split2(rb[i].x, rb[i].y, h, l);
                BH[(kq * 2) * PADW + row] = h;
                BL[(kq * 2) * PADW + row] = l;
                split2(rb[i].z, rb[i].w, h, l);
                BH[(kq * 2 + 1) * PADW + row] = h;
                BL[(kq * 2 + 1) * PADW + row] = l;
            }
        } else {
            int kp = t >> 5, n4 = (t & 31) * 4;
            const float f0[4] = {rb[0].x, rb[0].y, rb[0].z, rb[0].w};
            const float f1[4] = {rb[1].x, rb[1].y, rb[1].z, rb[1].w};
            unsigned h[4], l[4];
#pragma unroll
            for (int j = 0; j < 4; j++) split2(f0[j], f1[j], h[j], l[j]);
            *(uint4*)&BH[kp * PADW + n4] = make_uint4(h[0], h[1], h[2], h[3]);
            *(uint4*)&BL[kp * PADW + n4] = make_uint4(l[0], l[1], l[2], l[3]);
        }
    };

    load_tile(0);
    store_tile(0);
    __syncthreads();

    for (int kt = 0; kt < NK; kt++) {
        const int buf = kt & 1;
        if (kt + 1 < NK) load_tile(kt + 1);

        const unsigned* AH = sm + buf * BUFW;
        const unsigned* AL = AH + PLANE;
        const unsigned* BH = AH + 2 * PLANE;
        const unsigned* BL = AH + 3 * PLANE;

        // Phase 1: ah * bh
        unsigned ah[4][4], bh[4][2];
#pragma unroll
        for (int mt = 0; mt < 4; mt++) {
            int mo = aBase + mt * 16 + g;
            ah[mt][0] = AH[tg * PADW + mo];
            ah[mt][1] = AH[tg * PADW + mo + 8];
            ah[mt][2] = AH[(tg + 4) * PADW + mo];
            ah[mt][3] = AH[(tg + 4) * PADW + mo + 8];
        }
#pragma unroll
        for (int nt = 0; nt < 4; nt++) {
            int no = bBase + nt * 8 + g;
            bh[nt][0] = BH[tg * PADW + no];
            bh[nt][1] = BH[(tg + 4) * PADW + no];
        }
#pragma unroll
        for (int mt = 0; mt < 4; mt++)
#pragma unroll
            for (int nt = 0; nt < 4; nt++) mma16(acc[mt][nt], ah[mt], bh[nt]);

        // Phase 2: ah * bl
        {
            unsigned bl[4][2];
#pragma unroll
            for (int nt = 0; nt < 4; nt++) {
                int no = bBase + nt * 8 + g;
                bl[nt][0] = BL[tg * PADW + no];
                bl[nt][1] = BL[(tg + 4) * PADW + no];
            }
#pragma unroll
            for (int mt = 0; mt < 4; mt++)
#pragma unroll
                for (int nt = 0; nt < 4; nt++) mma16(acc[mt][nt], ah[mt], bl[nt]);
        }

        // Phase 3: al * bh
        {
            unsigned al[4][4];
#pragma unroll
            for (int mt = 0; mt < 4; mt++) {
                int mo = aBase + mt * 16 + g;
                al[mt][0] = AL[tg * PADW + mo];
                al[mt][1] = AL[tg * PADW + mo + 8];
                al[mt][2] = AL[(tg + 4) * PADW + mo];
                al[mt][3] = AL[(tg + 4) * PADW + mo + 8];
            }
#pragma unroll
            for (int mt = 0; mt < 4; mt++)
#pragma unroll
                for (int nt = 0; nt < 4; nt++) mma16(acc[mt][nt], al[mt], bh[nt]);
        }

        __syncthreads();
        if (kt + 1 < NK) {
            store_tile((kt + 1) & 1);
            __syncthreads();
        }
    }

    // --- epilogue ---
#pragma unroll
    for (int mt = 0; mt < 4; mt++) {
        int m = m0 + aBase + mt * 16 + g;
#pragma unroll
        for (int nt = 0; nt < 4; nt++) {
            int n = n0 + bBase + nt * 8 + tg * 2;
            float b0 = 0.f, b1 = 0.f;
            if (BIAS) { b0 = bias[n]; b1 = bias[n + 1]; }
            float2 v0 = make_float2(acc[mt][nt][0] * scale + b0,
                                    acc[mt][nt][1] * scale + b1);
            float2 v1 = make_float2(acc[mt][nt][2] * scale + b0,
                                    acc[mt][nt][3] * scale + b1);
            *(float2*)&C[(size_t)m * N + n] = v0;
            *(float2*)&C[(size_t)(m + 8) * N + n] = v1;
        }
    }
}

// ---------------------------------------------------------------------------
// Per-row exact top-k threshold (4-pass MSB radix select) + masked softmax.
// One block (256 threads) per row of 2048. Masked entries -> exactly 0.
// ---------------------------------------------------------------------------
__device__ __forceinline__ unsigned f2u(float f) {
    unsigned b = __float_as_uint(f);
    return (b & 0x80000000u) ? ~b : (b | 0x80000000u);
}
__device__ __forceinline__ float u2f(unsigned u) {
    unsigned b = (u & 0x80000000u) ? (u & 0x7fffffffu) : ~u;
    return __uint_as_float(b);
}

__global__ void __launch_bounds__(256) topk_softmax(float* __restrict__ S) {
    const size_t row = blockIdx.x;
    float* p = S + row * NN;
    const int tid = threadIdx.x;  // 256 threads, 8 elems each

    __shared__ int hist[256];
    __shared__ int s_digit, s_rem;
    __shared__ unsigned s_warpk[8];
    __shared__ float s_warpf[8];
    __shared__ float s_sum;

    unsigned key[8];
    float val[8];
    unsigned lmax = 0;
#pragma unroll
    for (int i = 0; i < 8; i++) {
        float f = p[tid + i * 256];
        val[i] = f;
        key[i] = f2u(f);
        lmax = max(lmax, key[i]);
    }

    lmax = __reduce_max_sync(0xffffffffu, lmax);
    if ((tid & 31) == 0) s_warpk[tid >> 5] = lmax;
    __syncthreads();
    if (tid == 0) {
        unsigned m = s_warpk[0];
#pragma unroll
        for (int w = 1; w < 8; w++) m = max(m, s_warpk[w]);
        s_warpk[0] = m;
        s_rem = KKEEP;
    }

    unsigned prefix = 0, pmask = 0;
    for (int shift = 24; shift >= 0; shift -= 8) {
        hist[tid] = 0;
        __syncthreads();
#pragma unroll
        for (int i = 0; i < 8; i++)
            if ((key[i] & pmask) == prefix)
                atomicAdd(&hist[(key[i] >> shift) & 255], 1);
        __syncthreads();
        if (tid == 0) {
            int remk = s_rem, cum = 0, d = 255;
            for (; d > 0; --d) {
                int c = hist[d];
                if (cum + c >= remk) break;
                cum += c;
            }
            s_digit = d;
            s_rem = remk - cum;
        }
        __syncthreads();
        prefix |= ((unsigned)s_digit) << shift;
        pmask |= 0xFFu << shift;
    }
    const unsigned thr = prefix;
    const float mval = u2f(s_warpk[0]);

    float e[8];
    float lsum = 0.f;
#pragma unroll
    for (int i = 0; i < 8; i++) {
        if (key[i] >= thr) {
            e[i] = __expf(val[i] - mval);
            lsum += e[i];
        } else {
            e[i] = 0.f;
        }
    }
#pragma unroll
    for (int o = 16; o > 0; o >>= 1) lsum += __shfl_down_sync(0xffffffffu, lsum, o);
    if ((tid & 31) == 0) s_warpf[tid >> 5] = lsum;
    __syncthreads();
    if (tid == 0) {
        float s = 0.f;
#pragma unroll
        for (int w = 0; w < 8; w++) s += s_warpf[w];
        s_sum = s;
    }
    __syncthreads();
    const float inv = 1.0f / s_sum;
#pragma unroll
    for (int i = 0; i < 8; i++) p[tid + i * 256] = e[i] * inv;
}

// ---------------------------------------------------------------------------
// Launch
// ---------------------------------------------------------------------------
extern "C" void kernel_launch(void* const* d_in, const int* in_sizes, int n_in,
                              void* d_out, int out_size) {
    const float* x  = (const float*)d_in[0];
    const float* Wq = (const float*)d_in[1];
    const float* bq = (const float*)d_in[2];
    const float* Wk = (const float*)d_in[3];
    const float* bk = (const float*)d_in[4];
    const float* Wv = (const float*)d_in[5];
    const float* bv = (const float*)d_in[6];
    float* out = (float*)d_out;

    float *Q, *K, *V, *S;
    cudaGetSymbolAddress((void**)&Q, g_Q);
    cudaGetSymbolAddress((void**)&K, g_K);
    cudaGetSymbolAddress((void**)&V, g_V);
    cudaGetSymbolAddress((void**)&S, g_S);

    dim3 thr(256);

    // QKV projections: [16384,1024] x [1024,1024]^T + bias
    dim3 gqkv(CC / 128, (BB * NN) / 128, 1);
    mma_gemm<true, true><<<gqkv, thr>>>(x, Wq, Q, bq, BB * NN, CC, CC, 0, 0, 0, 1.0f);
    mma_gemm<true, true><<<gqkv, thr>>>(x, Wk, K, bk, BB * NN, CC, CC, 0, 0, 0, 1.0f);
    mma_gemm<true, true><<<gqkv, thr>>>(x, Wv, V, bv, BB * NN, CC, CC, 0, 0, 0, 1.0f);

    // S = Q K^T / sqrt(C), batched over B
    dim3 gs(NN / 128, NN / 128, BB);
    mma_gemm<true, false><<<gs, thr>>>(Q, K, S, nullptr, NN, NN, CC,
                                       (long long)NN * CC, (long long)NN * CC,
                                       (long long)NN * NN, 0.03125f);

    // exact top-k mask + softmax (in place)
    topk_softmax<<<BB * NN, 256>>>(S);

    // O = P V, batched over B
    dim3 go(CC / 128, NN / 128, BB);
    mma_gemm<false, false><<<go, thr>>>(S, V, out, nullptr, NN, CC, NN,
                                        (long long)NN * NN, (long long)NN * CC,
                                        (long long)NN * CC, 1.0f);
}